// round 16
// baseline (speedup 1.0000x reference)
#include <cuda_runtime.h>
#include <cstdint>
#include <cfloat>

// Problem constants (fixed by the reference)
#define NB   8192
#define EMB  768
#define NP   96
#define NK   256
#define ND   8
#define NKP  (NK / 2)        // 128 k-pair steps
#define NGRP (NKP / 2)       // 64 groups of 2 steps = 4 codes

#define THREADS      128
#define ROWS_PER_T   4
#define ROWS_PER_BLK (THREADS * ROWS_PER_T)   // 512
#define GRID_X       (NB / ROWS_PER_BLK)      // 16

#define GRP_STRIDE   20      // u64 per group record (8+8 dims + 2 c2 + pad)
#define GRP_BYTES    160

typedef unsigned long long u64;

__device__ __forceinline__ u64 ffma2(u64 a, u64 b, u64 c) {
    u64 d;
    asm("fma.rn.f32x2 %0, %1, %2, %3;" : "=l"(d) : "l"(a), "l"(b), "l"(c));
    return d;
}
__device__ __forceinline__ u64 pack2(float lo, float hi) {
    u64 r;
    asm("mov.b64 %0, {%1, %2};" : "=l"(r) : "f"(lo), "f"(hi));
    return r;
}
__device__ __forceinline__ void unpack2(u64 v, float& lo, float& hi) {
    asm("mov.b64 {%0, %1}, %2;" : "=f"(lo), "=f"(hi) : "l"(v));
}
__device__ __forceinline__ uint32_t smem_u32(const void* p) {
    uint32_t a;
    asm("{ .reg .u64 t; cvta.to.shared.u64 t, %1; cvt.u32.u64 %0, t; }"
        : "=r"(a) : "l"(p));
    return a;
}
// Batched, opaque shared load: ptxas cannot split it or sink it into the
// consumer stream. Two u64 per call (one LDS.128).
#define LDS_V2U64(lo, hi, addr) \
    asm volatile("ld.shared.v2.u64 {%0, %1}, [%2];" \
                 : "=l"(lo), "=l"(hi) : "r"(addr))

// Exact score chain over 8 explicit q regs — serially dependent, so the
// pass-2 recomputation (same order) is bit-identical.
__device__ __forceinline__ u64 score8(u64 c2,
                                      u64 q0, u64 q1, u64 q2, u64 q3,
                                      u64 q4, u64 q5, u64 q6, u64 q7,
                                      const u64* vd) {
    u64 acc = c2;
    acc = ffma2(vd[0], q0, acc);
    acc = ffma2(vd[1], q1, acc);
    acc = ffma2(vd[2], q2, acc);
    acc = ffma2(vd[3], q3, acc);
    acc = ffma2(vd[4], q4, acc);
    acc = ffma2(vd[5], q5, acc);
    acc = ffma2(vd[6], q6, acc);
    acc = ffma2(vd[7], q7, acc);
    return acc;
}

__global__ __launch_bounds__(THREADS, 5)
void pq_argmin_kernel(const float* __restrict__ vecs,
                      const float* __restrict__ codebook,
                      float* __restrict__ out) {
    // Group record (4 codes): [0..7] step-A dims, [8..15] step-B dims,
    // [16..17] the two c2 pairs, [18..19] pad. Stride 160B.
    __shared__ __align__(16) u64 s_grp[NGRP][GRP_STRIDE];  // 10.24 KB

    const int p   = blockIdx.y;
    const int tid = threadIdx.x;

    // ---- stage codebook[p]: thread t handles code pair (2t, 2t+1) ----
    {
        const int g    = tid >> 1;   // group
        const int half = tid & 1;    // 0 = step A, 1 = step B
        const float4* cb = reinterpret_cast<const float4*>(
            codebook + ((size_t)p * NK + 2 * tid) * ND);   // coalesced 64B/thread
        float4 a0 = cb[0], a1 = cb[1];   // code 2t
        float4 b0 = cb[2], b1 = cb[3];   // code 2t+1
        float c2a = a0.x*a0.x + a0.y*a0.y + a0.z*a0.z + a0.w*a0.w
                  + a1.x*a1.x + a1.y*a1.y + a1.z*a1.z + a1.w*a1.w;
        float c2b = b0.x*b0.x + b0.y*b0.y + b0.z*b0.z + b0.w*b0.w
                  + b1.x*b1.x + b1.y*b1.y + b1.z*b1.z + b1.w*b1.w;
        u64* rec = s_grp[g] + 8 * half;
        rec[0] = pack2(-2.f*a0.x, -2.f*b0.x);
        rec[1] = pack2(-2.f*a0.y, -2.f*b0.y);
        rec[2] = pack2(-2.f*a0.z, -2.f*b0.z);
        rec[3] = pack2(-2.f*a0.w, -2.f*b0.w);
        rec[4] = pack2(-2.f*a1.x, -2.f*b1.x);
        rec[5] = pack2(-2.f*a1.y, -2.f*b1.y);
        rec[6] = pack2(-2.f*a1.z, -2.f*b1.z);
        rec[7] = pack2(-2.f*a1.w, -2.f*b1.w);
        s_grp[g][16 + half] = pack2(c2a, c2b);
    }
    __syncthreads();

    // ---- load 4 rows' v-slices via ONE base pointer + immediate offsets ----
    const float* vbase =
        vecs + (size_t)(blockIdx.x * ROWS_PER_BLK + tid) * EMB + p * ND;

    // v duplicated into both f32x2 lanes; vd only indexed by constants.
    u64 vd[ROWS_PER_T][ND];
#pragma unroll
    for (int r = 0; r < ROWS_PER_T; r++) {
        const float4* g4 = reinterpret_cast<const float4*>(
            vbase + (size_t)r * THREADS * EMB);
        float4 a = g4[0], b = g4[1];
        vd[r][0] = pack2(a.x, a.x);
        vd[r][1] = pack2(a.y, a.y);
        vd[r][2] = pack2(a.z, a.z);
        vd[r][3] = pack2(a.w, a.w);
        vd[r][4] = pack2(b.x, b.x);
        vd[r][5] = pack2(b.y, b.y);
        vd[r][6] = pack2(b.z, b.z);
        vd[r][7] = pack2(b.w, b.w);
    }

    float best0 = FLT_MAX, best1 = FLT_MAX, best2 = FLT_MAX, best3 = FLT_MAX;
    int   bg0 = 0, bg1 = 0, bg2 = 0, bg3 = 0;

    uint32_t saddr = smem_u32(&s_grp[0][0]);

    // ---- main loop: 64 groups of 2 pair-steps (4 codes each).
    //      All LDS for a phase issued back-to-back as opaque volatile asm:
    //      ONE pipelined latency exposure per phase instead of one per load. ----
#pragma unroll 1
    for (int g = 0; g < NGRP; g++) {
        // phase A loads: 4 q-vectors + both c2 pairs, batched (MLP=5)
        u64 a0, a1, a2, a3, a4, a5, a6, a7, c2A, c2B;
        LDS_V2U64(a0, a1, saddr);
        LDS_V2U64(a2, a3, saddr + 16);
        LDS_V2U64(a4, a5, saddr + 32);
        LDS_V2U64(a6, a7, saddr + 48);
        LDS_V2U64(c2A, c2B, saddr + 128);

        float sa, sb;
        u64 acc;
        acc = score8(c2A, a0, a1, a2, a3, a4, a5, a6, a7, vd[0]);
        unpack2(acc, sa, sb); float m00 = fminf(sa, sb);
        acc = score8(c2A, a0, a1, a2, a3, a4, a5, a6, a7, vd[1]);
        unpack2(acc, sa, sb); float m01 = fminf(sa, sb);
        acc = score8(c2A, a0, a1, a2, a3, a4, a5, a6, a7, vd[2]);
        unpack2(acc, sa, sb); float m02 = fminf(sa, sb);
        acc = score8(c2A, a0, a1, a2, a3, a4, a5, a6, a7, vd[3]);
        unpack2(acc, sa, sb); float m03 = fminf(sa, sb);

        // phase B loads: 4 q-vectors, batched (MLP=4)
        u64 b0, b1, b2, b3, b4, b5, b6, b7;
        LDS_V2U64(b0, b1, saddr + 64);
        LDS_V2U64(b2, b3, saddr + 80);
        LDS_V2U64(b4, b5, saddr + 96);
        LDS_V2U64(b6, b7, saddr + 112);

        float m;
        acc = score8(c2B, b0, b1, b2, b3, b4, b5, b6, b7, vd[0]);
        unpack2(acc, sa, sb);
        m = fminf(m00, fminf(sa, sb));
        bg0 = (m < best0) ? g : bg0;       // SEL (pred-as-data), earliest g on ties
        best0 = fminf(best0, m);

        acc = score8(c2B, b0, b1, b2, b3, b4, b5, b6, b7, vd[1]);
        unpack2(acc, sa, sb);
        m = fminf(m01, fminf(sa, sb));
        bg1 = (m < best1) ? g : bg1;
        best1 = fminf(best1, m);

        acc = score8(c2B, b0, b1, b2, b3, b4, b5, b6, b7, vd[2]);
        unpack2(acc, sa, sb);
        m = fminf(m02, fminf(sa, sb));
        bg2 = (m < best2) ? g : bg2;
        best2 = fminf(best2, m);

        acc = score8(c2B, b0, b1, b2, b3, b4, b5, b6, b7, vd[3]);
        unpack2(acc, sa, sb);
        m = fminf(m03, fminf(sa, sb));
        bg3 = (m < best3) ? g : bg3;
        best3 = fminf(best3, m);

        saddr += GRP_BYTES;
    }

    const float bestA[ROWS_PER_T] = {best0, best1, best2, best3};
    const int   bgA  [ROWS_PER_T] = {bg0, bg1, bg2, bg3};

    // ---- fused: resolve index inside winning group (bit-exact recompute)
    //      + gather + store. r-loop fully unrolled (static vd indexing);
    //      dynamic indexing touches smem only. ----
    float* obase =
        out + (size_t)(blockIdx.x * ROWS_PER_BLK + tid) * EMB + p * ND;
#pragma unroll
    for (int r = 0; r < ROWS_PER_T; r++) {
        const int gw = bgA[r];
        const u64* rec = s_grp[gw];
        u64 accA = score8(rec[16], rec[0], rec[1], rec[2], rec[3],
                          rec[4], rec[5], rec[6], rec[7], vd[r]);
        u64 accB = score8(rec[17], rec[8], rec[9], rec[10], rec[11],
                          rec[12], rec[13], rec[14], rec[15], vd[r]);
        float sa0, sb0, sa1, sb1;
        unpack2(accA, sa0, sb0);
        unpack2(accB, sa1, sb1);
        // ascending priority => lowest k wins exact ties (jnp.argmax semantics)
        int k = 4 * gw + 3;
        if (sa1 == bestA[r]) k = 4 * gw + 2;
        if (sb0 == bestA[r]) k = 4 * gw + 1;
        if (sa0 == bestA[r]) k = 4 * gw;

        // gather winning code; c = (-2c) * -0.5 is bit-exact.
        // code k: group k>>2, half (k>>1)&1, lane k&1.
        const float* h = reinterpret_cast<const float*>(
            s_grp[k >> 2] + 8 * ((k >> 1) & 1)) + (k & 1);
        float4 oa, ob;
        oa.x = -0.5f * h[0];
        oa.y = -0.5f * h[2];
        oa.z = -0.5f * h[4];
        oa.w = -0.5f * h[6];
        ob.x = -0.5f * h[8];
        ob.y = -0.5f * h[10];
        ob.z = -0.5f * h[12];
        ob.w = -0.5f * h[14];
        float4* o = reinterpret_cast<float4*>(obase + (size_t)r * THREADS * EMB);
        o[0] = oa;
        o[1] = ob;
    }
}

extern "C" void kernel_launch(void* const* d_in, const int* in_sizes, int n_in,
                              void* d_out, int out_size) {
    const float* vecs     = (const float*)d_in[0];   // [8192, 768] f32
    const float* codebook = (const float*)d_in[1];   // [96, 256, 8] f32
    float* out            = (float*)d_out;           // [8192, 768] f32

    dim3 grid(GRID_X, NP);
    dim3 block(THREADS);
    pq_argmin_kernel<<<grid, block>>>(vecs, codebook, out);
}

// round 17
// speedup vs baseline: 1.0749x; 1.0749x over previous
#include <cuda_runtime.h>
#include <cstdint>
#include <cfloat>

// Problem constants (fixed by the reference)
#define NB   8192
#define EMB  768
#define NP   96
#define NK   256
#define ND   8
#define NKP  (NK / 2)        // 128 k-pair steps
#define NGRP (NKP / 2)       // 64 groups of 2 steps = 4 codes

#define THREADS      128
#define ROWS_PER_T   4
#define ROWS_PER_BLK (THREADS * ROWS_PER_T)   // 512
#define GRID_X       (NB / ROWS_PER_BLK)      // 16

#define GRP_STRIDE   20      // u64 per group record (8+8 dims + 2 c2 + pad)
#define GRP_BYTES    160

typedef unsigned long long u64;

__device__ __forceinline__ u64 ffma2(u64 a, u64 b, u64 c) {
    u64 d;
    asm("fma.rn.f32x2 %0, %1, %2, %3;" : "=l"(d) : "l"(a), "l"(b), "l"(c));
    return d;
}
__device__ __forceinline__ u64 pack2(float lo, float hi) {
    u64 r;
    asm("mov.b64 %0, {%1, %2};" : "=l"(r) : "f"(lo), "f"(hi));
    return r;
}
__device__ __forceinline__ void unpack2(u64 v, float& lo, float& hi) {
    asm("mov.b64 {%0, %1}, %2;" : "=f"(lo), "=f"(hi) : "l"(v));
}
__device__ __forceinline__ uint32_t smem_u32(const void* p) {
    uint32_t a;
    asm("{ .reg .u64 t; cvta.to.shared.u64 t, %1; cvt.u32.u64 %0, t; }"
        : "=r"(a) : "l"(p));
    return a;
}
// Opaque, order-pinned shared load (volatile asms keep mutual program order;
// ptxas cannot sink them to their consumers). One LDS.128.
#define LDS_V2U64(lo, hi, addr) \
    asm volatile("ld.shared.v2.u64 {%0, %1}, [%2];" \
                 : "=l"(lo), "=l"(hi) : "r"(addr))

// Exact score chain over 8 explicit q regs — serially dependent, so the
// pass-2 recomputation (same order) is bit-identical.
__device__ __forceinline__ u64 score8(u64 c2,
                                      u64 q0, u64 q1, u64 q2, u64 q3,
                                      u64 q4, u64 q5, u64 q6, u64 q7,
                                      const u64* vd) {
    u64 acc = c2;
    acc = ffma2(vd[0], q0, acc);
    acc = ffma2(vd[1], q1, acc);
    acc = ffma2(vd[2], q2, acc);
    acc = ffma2(vd[3], q3, acc);
    acc = ffma2(vd[4], q4, acc);
    acc = ffma2(vd[5], q5, acc);
    acc = ffma2(vd[6], q6, acc);
    acc = ffma2(vd[7], q7, acc);
    return acc;
}

__global__ __launch_bounds__(THREADS, 4)
void pq_argmin_kernel(const float* __restrict__ vecs,
                      const float* __restrict__ codebook,
                      float* __restrict__ out) {
    // Group record (4 codes): [0..7] step-A dims, [8..15] step-B dims,
    // [16..17] the two c2 pairs, [18..19] pad. Stride 160B.
    // +1 pad group: the steady-state prefetch of group g+1 overruns by one
    // on the last iteration; the pad keeps it in-bounds (values unused).
    __shared__ __align__(16) u64 s_grp[NGRP + 1][GRP_STRIDE];  // 10.4 KB

    const int p   = blockIdx.y;
    const int tid = threadIdx.x;

    // ---- stage codebook[p]: thread t handles code pair (2t, 2t+1) ----
    {
        const int g    = tid >> 1;   // group
        const int half = tid & 1;    // 0 = step A, 1 = step B
        const float4* cb = reinterpret_cast<const float4*>(
            codebook + ((size_t)p * NK + 2 * tid) * ND);   // coalesced 64B/thread
        float4 a0 = cb[0], a1 = cb[1];   // code 2t
        float4 b0 = cb[2], b1 = cb[3];   // code 2t+1
        float c2a = a0.x*a0.x + a0.y*a0.y + a0.z*a0.z + a0.w*a0.w
                  + a1.x*a1.x + a1.y*a1.y + a1.z*a1.z + a1.w*a1.w;
        float c2b = b0.x*b0.x + b0.y*b0.y + b0.z*b0.z + b0.w*b0.w
                  + b1.x*b1.x + b1.y*b1.y + b1.z*b1.z + b1.w*b1.w;
        u64* rec = s_grp[g] + 8 * half;
        rec[0] = pack2(-2.f*a0.x, -2.f*b0.x);
        rec[1] = pack2(-2.f*a0.y, -2.f*b0.y);
        rec[2] = pack2(-2.f*a0.z, -2.f*b0.z);
        rec[3] = pack2(-2.f*a0.w, -2.f*b0.w);
        rec[4] = pack2(-2.f*a1.x, -2.f*b1.x);
        rec[5] = pack2(-2.f*a1.y, -2.f*b1.y);
        rec[6] = pack2(-2.f*a1.z, -2.f*b1.z);
        rec[7] = pack2(-2.f*a1.w, -2.f*b1.w);
        s_grp[g][16 + half] = pack2(c2a, c2b);
    }
    __syncthreads();

    // ---- load 4 rows' v-slices via ONE base pointer + immediate offsets ----
    const float* vbase =
        vecs + (size_t)(blockIdx.x * ROWS_PER_BLK + tid) * EMB + p * ND;

    // v duplicated into both f32x2 lanes; vd only indexed by constants.
    u64 vd[ROWS_PER_T][ND];
#pragma unroll
    for (int r = 0; r < ROWS_PER_T; r++) {
        const float4* g4 = reinterpret_cast<const float4*>(
            vbase + (size_t)r * THREADS * EMB);
        float4 a = g4[0], b = g4[1];
        vd[r][0] = pack2(a.x, a.x);
        vd[r][1] = pack2(a.y, a.y);
        vd[r][2] = pack2(a.z, a.z);
        vd[r][3] = pack2(a.w, a.w);
        vd[r][4] = pack2(b.x, b.x);
        vd[r][5] = pack2(b.y, b.y);
        vd[r][6] = pack2(b.z, b.z);
        vd[r][7] = pack2(b.w, b.w);
    }

    float best0 = FLT_MAX, best1 = FLT_MAX, best2 = FLT_MAX, best3 = FLT_MAX;
    int   bg0 = 0, bg1 = 0, bg2 = 0, bg3 = 0;

    uint32_t saddr = smem_u32(&s_grp[0][0]);

    // ---- software pipeline prologue: phase A of group 0 in flight ----
    u64 aq0, aq1, aq2, aq3, aq4, aq5, aq6, aq7, c2A, c2B;
    LDS_V2U64(aq0, aq1, saddr);
    LDS_V2U64(aq2, aq3, saddr + 16);
    LDS_V2U64(aq4, aq5, saddr + 32);
    LDS_V2U64(aq6, aq7, saddr + 48);
    LDS_V2U64(c2A, c2B, saddr + 128);

    // ---- main loop: loads for the NEXT phase are issued (volatile, order-
    //      pinned) BEFORE the current phase's compute, so L1tex queue time
    //      overlaps FFMA2 time instead of alternating with it. ----
#pragma unroll 1
    for (int g = 0; g < NGRP; g++) {
        // prefetch phase B of group g (4 LDS, in flight during compute A)
        u64 b0, b1, b2, b3, b4, b5, b6, b7;
        LDS_V2U64(b0, b1, saddr + 64);
        LDS_V2U64(b2, b3, saddr + 80);
        LDS_V2U64(b4, b5, saddr + 96);
        LDS_V2U64(b6, b7, saddr + 112);

        // compute phase A (codes 4g, 4g+1) from prefetched registers
        float sa, sb;
        u64 acc;
        acc = score8(c2A, aq0, aq1, aq2, aq3, aq4, aq5, aq6, aq7, vd[0]);
        unpack2(acc, sa, sb); float m00 = fminf(sa, sb);
        acc = score8(c2A, aq0, aq1, aq2, aq3, aq4, aq5, aq6, aq7, vd[1]);
        unpack2(acc, sa, sb); float m01 = fminf(sa, sb);
        acc = score8(c2A, aq0, aq1, aq2, aq3, aq4, aq5, aq6, aq7, vd[2]);
        unpack2(acc, sa, sb); float m02 = fminf(sa, sb);
        acc = score8(c2A, aq0, aq1, aq2, aq3, aq4, aq5, aq6, aq7, vd[3]);
        unpack2(acc, sa, sb); float m03 = fminf(sa, sb);

        // prefetch phase A of group g+1 (5 LDS, in flight during compute B;
        // last iteration reads the pad group — values never consumed)
        saddr += GRP_BYTES;
        u64 na0, na1, na2, na3, na4, na5, na6, na7, nc2A, nc2B;
        LDS_V2U64(na0, na1, saddr);
        LDS_V2U64(na2, na3, saddr + 16);
        LDS_V2U64(na4, na5, saddr + 32);
        LDS_V2U64(na6, na7, saddr + 48);
        LDS_V2U64(nc2A, nc2B, saddr + 128);

        // compute phase B (codes 4g+2, 4g+3) + bookkeeping
        float m;
        acc = score8(c2B, b0, b1, b2, b3, b4, b5, b6, b7, vd[0]);
        unpack2(acc, sa, sb);
        m = fminf(m00, fminf(sa, sb));
        bg0 = (m < best0) ? g : bg0;       // SEL (pred-as-data), earliest g on ties
        best0 = fminf(best0, m);

        acc = score8(c2B, b0, b1, b2, b3, b4, b5, b6, b7, vd[1]);
        unpack2(acc, sa, sb);
        m = fminf(m01, fminf(sa, sb));
        bg1 = (m < best1) ? g : bg1;
        best1 = fminf(best1, m);

        acc = score8(c2B, b0, b1, b2, b3, b4, b5, b6, b7, vd[2]);
        unpack2(acc, sa, sb);
        m = fminf(m02, fminf(sa, sb));
        bg2 = (m < best2) ? g : bg2;
        best2 = fminf(best2, m);

        acc = score8(c2B, b0, b1, b2, b3, b4, b5, b6, b7, vd[3]);
        unpack2(acc, sa, sb);
        m = fminf(m03, fminf(sa, sb));
        bg3 = (m < best3) ? g : bg3;
        best3 = fminf(best3, m);

        // rotate prefetch buffer into place
        aq0 = na0; aq1 = na1; aq2 = na2; aq3 = na3;
        aq4 = na4; aq5 = na5; aq6 = na6; aq7 = na7;
        c2A = nc2A; c2B = nc2B;
    }

    const float bestA[ROWS_PER_T] = {best0, best1, best2, best3};
    const int   bgA  [ROWS_PER_T] = {bg0, bg1, bg2, bg3};

    // ---- fused: resolve index inside winning group (bit-exact recompute)
    //      + gather + store. r-loop fully unrolled (static vd indexing);
    //      dynamic indexing touches smem only. ----
    float* obase =
        out + (size_t)(blockIdx.x * ROWS_PER_BLK + tid) * EMB + p * ND;
#pragma unroll
    for (int r = 0; r < ROWS_PER_T; r++) {
        const int gw = bgA[r];
        const u64* rec = s_grp[gw];
        u64 accA = score8(rec[16], rec[0], rec[1], rec[2], rec[3],
                          rec[4], rec[5], rec[6], rec[7], vd[r]);
        u64 accB = score8(rec[17], rec[8], rec[9], rec[10], rec[11],
                          rec[12], rec[13], rec[14], rec[15], vd[r]);
        float sa0, sb0, sa1, sb1;
        unpack2(accA, sa0, sb0);
        unpack2(accB, sa1, sb1);
        // ascending priority => lowest k wins exact ties (jnp.argmax semantics)
        int k = 4 * gw + 3;
        if (sa1 == bestA[r]) k = 4 * gw + 2;
        if (sb0 == bestA[r]) k = 4 * gw + 1;
        if (sa0 == bestA[r]) k = 4 * gw;

        // gather winning code; c = (-2c) * -0.5 is bit-exact.
        // code k: group k>>2, half (k>>1)&1, lane k&1.
        const float* h = reinterpret_cast<const float*>(
            s_grp[k >> 2] + 8 * ((k >> 1) & 1)) + (k & 1);
        float4 oa, ob;
        oa.x = -0.5f * h[0];
        oa.y = -0.5f * h[2];
        oa.z = -0.5f * h[4];
        oa.w = -0.5f * h[6];
        ob.x = -0.5f * h[8];
        ob.y = -0.5f * h[10];
        ob.z = -0.5f * h[12];
        ob.w = -0.5f * h[14];
        float4* o = reinterpret_cast<float4*>(obase + (size_t)r * THREADS * EMB);
        o[0] = oa;
        o[1] = ob;
    }
}

extern "C" void kernel_launch(void* const* d_in, const int* in_sizes, int n_in,
                              void* d_out, int out_size) {
    const float* vecs     = (const float*)d_in[0];   // [8192, 768] f32
    const float* codebook = (const float*)d_in[1];   // [96, 256, 8] f32
    float* out            = (float*)d_out;           // [8192, 768] f32

    dim3 grid(GRID_X, NP);
    dim3 block(THREADS);
    pq_argmin_kernel<<<grid, block>>>(vecs, codebook, out);
}